// round 14
// baseline (speedup 1.0000x reference)
#include <cuda_runtime.h>
#include <cuda_bf16.h>
#include <cstdint>

__host__ __device__ constexpr int PC4(int x) {
    return ((x >> 0) & 1) + ((x >> 1) & 1) + ((x >> 2) & 1) + ((x >> 3) & 1);
}
__host__ __device__ constexpr float SGN(int a, int b) {
    int s = 0; int aa = a >> 1;
    while (aa) { s += PC4(aa & b); aa >>= 1; }
    return (s & 1) ? -1.0f : 1.0f;
}
struct GPTab { int a[192]; int b[192]; int k[192]; float s[192]; };
__host__ __device__ constexpr GPTab make_gp() {
    GPTab t{}; int n = 0;
    for (int a = 0; a < 16; a++)
        for (int b = 0; b < 16; b++)
            if (!(a & b & 1)) { t.a[n]=a; t.b[n]=b; t.k[n]=a^b; t.s[n]=SGN(a,b); n++; }
    return t;
}
struct JTab { int a[81]; int b[81]; int k[81]; float s[81]; };
__host__ __device__ constexpr JTab make_j() {
    JTab t{}; int n = 0;
    for (int i = 0; i < 16; i++)
        for (int j = 0; j < 16; j++)
            if ((i | j) == 15) {
                int p = i^15, q = j^15, k = i&j, r = k^15;
                t.a[n]=i; t.b[n]=j; t.k[n]=k;
                t.s[n]=SGN(i,p)*SGN(j,q)*SGN(p,q)*SGN(k,r); n++;
            }
    return t;
}
__device__ constexpr GPTab GPT = make_gp();
__device__ constexpr JTab  JT  = make_j();
__device__ constexpr int PCY[16] = {0,1,1,2,1,2,2,3,1,2,2,3,2,3,3,4};

#define MMA(d, a, b) \
    asm("mma.sync.aligned.m16n8k16.row.col.f32.bf16.bf16.f32 " \
        "{%0,%1,%2,%3}, {%4,%5,%6,%7}, {%8,%9}, {%0,%1,%2,%3};" \
        : "+f"(d[0]), "+f"(d[1]), "+f"(d[2]), "+f"(d[3]) \
        : "r"(a[0]), "r"(a[1]), "r"(a[2]), "r"(a[3]), "r"(b[0]), "r"(b[1]))

__device__ __forceinline__ void ldmx4(uint32_t* r, uint32_t a) {
    asm volatile("ldmatrix.sync.aligned.m8n8.x4.shared.b16 {%0,%1,%2,%3}, [%4];"
        : "=r"(r[0]), "=r"(r[1]), "=r"(r[2]), "=r"(r[3]) : "r"(a));
}
__device__ __forceinline__ void ldmx2(uint32_t* r, uint32_t a) {
    asm volatile("ldmatrix.sync.aligned.m8n8.x2.shared.b16 {%0,%1}, [%2];"
        : "=r"(r[0]), "=r"(r[1]) : "r"(a));
}
__device__ __forceinline__ uint32_t smem_u32(const void* p) {
    uint32_t a;
    asm("{ .reg .u64 t; cvta.to.shared.u64 t, %1; cvt.u32.u64 %0, t; }" : "=r"(a) : "l"(p));
    return a;
}

#define THREADS 256
#define JSTR 144
#define WPL  (32 * JSTR)
#define WSM_BYTES (36 * WPL)        // 165888
#define PSTR 48
#define YPL  (32 * PSTR + 16)       // 1552
#define XHL  (16 * YPL)             // 24832
#define XSM_BYTES (2 * XHL)
#define SMEM_BYTES (WSM_BYTES + XSM_BYTES)

__global__ __launch_bounds__(THREADS, 1)
void gbl_kernel(const float* __restrict__ x, const float* __restrict__ ref,
                const float* __restrict__ wg1, const float* __restrict__ wg2,
                const float* __restrict__ wj1, const float* __restrict__ wj2,
                float* __restrict__ out, int nPos)
{
    extern __shared__ char sm[];
    char* wsm = sm;
    char* xsm = sm + WSM_BYTES;

    const int tid  = threadIdx.x;
    const int wid  = tid >> 5;
    const int lane = tid & 31;
    const int pt = wid >> 2;
    const int jt = wid & 3;
    const int r  = lane >> 2;
    const int q  = lane & 3;

    const int group  = blockIdx.y;
    const int branch = group >> 1;
    const int chalf  = group & 1;
    const float* wA = branch ? wj1 : wg1;
    const float* wB = branch ? wj2 : wg2;

    for (int e = tid; e < 36864; e += THREADS) {
        int ws = e / 18432;
        int rem = e - ws * 18432;
        int j = rem / 576;
        int rem2 = rem - j * 576;
        int i = rem2 / 9;
        int b = rem2 - i * 9;
        const float* src = ws ? wB : wA;
        float v = src[(chalf * 32 + j) * 576 + i * 9 + b];
        __nv_bfloat16 h = __float2bfloat16(v);
        __nv_bfloat16 l = __float2bfloat16(v - __bfloat162float(h));
        char* rp = wsm + ((ws * 9 + b) * 2) * WPL + j * JSTR + i * 2;
        *(__nv_bfloat16*)rp = h;
        *(__nv_bfloat16*)(rp + WPL) = l;
    }

    const int cout = branch * 64 + chalf * 32 + jt * 8 + 2 * q;
    const int nChunk = nPos >> 5;
    const float4* xg4 = (const float4*)x;

    const uint32_t wlm = smem_u32(wsm) + (jt * 8 + (lane & 7)) * JSTR
                         + ((lane >> 3) & 1) * 16;
    const uint32_t xlm = smem_u32(xsm)
                         + (pt * 16 + ((lane >> 3) & 1) * 8 + (lane & 7)) * PSTR
                         + (lane >> 4) * 16;

    const int sq4 = tid & 3, sip = (tid >> 2) & 7;
    const int spp[4] = {tid >> 5, (tid + THREADS) >> 5,
                        (tid + 2 * THREADS) >> 5, (tid + 3 * THREADS) >> 5};
    const int half = sq4 >> 1;   // 0: this thread's quad is in y0-7, 1: y8-15

    // ---- prefetch first k-block of first chunk ----
    float4 pf[8];
    #pragma unroll
    for (int k = 0; k < 4; k++) {
        const float4* g = xg4 + ((size_t)((blockIdx.x << 5) + spp[k]) * 64 + 2 * sip) * 4 + sq4;
        pf[2 * k]     = g[0];
        pf[2 * k + 1] = g[4];
    }

    __syncthreads();   // weights staged

    // ---- preamble: stage half0 (y0-7) of first ib ----
    #pragma unroll
    for (int k = 0; k < 4; k++) {
        if (half == 0) {
            float e0[4] = {pf[2*k].x, pf[2*k].y, pf[2*k].z, pf[2*k].w};
            float e1[4] = {pf[2*k+1].x, pf[2*k+1].y, pf[2*k+1].z, pf[2*k+1].w};
            #pragma unroll
            for (int c = 0; c < 4; c++) {
                int y = sq4 * 4 + c;
                __nv_bfloat16 h0 = __float2bfloat16(e0[c]);
                __nv_bfloat16 h1 = __float2bfloat16(e1[c]);
                __nv_bfloat16 l0 = __float2bfloat16(e0[c] - __bfloat162float(h0));
                __nv_bfloat16 l1 = __float2bfloat16(e1[c] - __bfloat162float(h1));
                uint32_t hw = (uint32_t)__bfloat16_as_ushort(h0) | ((uint32_t)__bfloat16_as_ushort(h1) << 16);
                uint32_t lw = (uint32_t)__bfloat16_as_ushort(l0) | ((uint32_t)__bfloat16_as_ushort(l1) << 16);
                char* d0 = xsm + y * YPL + spp[k] * PSTR + sip * 4;
                *(uint32_t*)d0 = hw;
                *(uint32_t*)(d0 + XHL) = lw;
            }
        }
    }
    __syncthreads();

    for (int chunk = blockIdx.x; chunk < nChunk; chunk += gridDim.x) {
        const int p0 = chunk << 5;

        float D[2][16][4];
        #pragma unroll
        for (int ws = 0; ws < 2; ws++)
            #pragma unroll
            for (int y = 0; y < 16; y++)
                #pragma unroll
                for (int k = 0; k < 4; k++) D[ws][y][k] = 0.0f;

        for (int ib = 0; ib < 4; ib++) {
            int nib = ib + 1;
            int nch = chunk;
            if (nib == 4) { nib = 0; nch = chunk + gridDim.x; }
            const bool vnext = (nch < nChunk);

            // ================= phase A =================
            // STS half1 (y8-15) of current ib from pf
            #pragma unroll
            for (int k = 0; k < 4; k++) {
                if (half == 1) {
                    float e0[4] = {pf[2*k].x, pf[2*k].y, pf[2*k].z, pf[2*k].w};
                    float e1[4] = {pf[2*k+1].x, pf[2*k+1].y, pf[2*k+1].z, pf[2*k+1].w};
                    #pragma unroll
                    for (int c = 0; c < 4; c++) {
                        int y = sq4 * 4 + c;
                        __nv_bfloat16 h0 = __float2bfloat16(e0[c]);
                        __nv_bfloat16 h1 = __float2bfloat16(e1[c]);
                        __nv_bfloat16 l0 = __float2bfloat16(e0[c] - __bfloat162float(h0));
                        __nv_bfloat16 l1 = __float2bfloat16(e1[c] - __bfloat162float(h1));
                        uint32_t hw = (uint32_t)__bfloat16_as_ushort(h0) | ((uint32_t)__bfloat16_as_ushort(h1) << 16);
                        uint32_t lw = (uint32_t)__bfloat16_as_ushort(l0) | ((uint32_t)__bfloat16_as_ushort(l1) << 16);
                        char* d0 = xsm + y * YPL + spp[k] * PSTR + sip * 4;
                        *(uint32_t*)d0 = hw;
                        *(uint32_t*)(d0 + XHL) = lw;
                    }
                }
            }
            // prefetch next k-block (pf halves already consumed or consumed this phase)
            if (vnext) {
                const int np0 = nch << 5;
                #pragma unroll
                for (int k = 0; k < 4; k++) {
                    const float4* g = xg4 + ((size_t)(np0 + spp[k]) * 64 + nib * 16 + 2 * sip) * 4 + sq4;
                    pf[2 * k]     = g[0];
                    pf[2 * k + 1] = g[4];
                }
            }
            // hi w fragments for this ib
            uint32_t Bh[2][9][2];
            const uint32_t wk = wlm + ib * 32;
            #pragma unroll
            for (int ws = 0; ws < 2; ws++)
                #pragma unroll
                for (int b = 0; b < 9; b++)
                    ldmx2(Bh[ws][b], wk + ((ws * 9 + b) * 2) * WPL);

            // MMA t = 0..3 (reads y0-7, staged one phase earlier)
            #pragma unroll
            for (int t = 0; t < 4; t++) {
                const int ye = 2 * t, yo = 2 * t + 1;
                const int pe = PCY[ye], po = PCY[yo], bs = 4 + po;
                uint32_t Ax[2][2][4];
                #pragma unroll
                for (int yy = 0; yy < 2; yy++)
                    #pragma unroll
                    for (int hl = 0; hl < 2; hl++)
                        ldmx4(Ax[yy][hl], xlm + hl * XHL + (ye + yy) * YPL);
                uint32_t Blp[2][2], Blo[2][2], Blb[2][2];
                #pragma unroll
                for (int ws = 0; ws < 2; ws++) {
                    ldmx2(Blp[ws], wk + ((ws * 9 + pe) * 2 + 1) * WPL);
                    ldmx2(Blo[ws], wk + ((ws * 9 + po) * 2 + 1) * WPL);
                    ldmx2(Blb[ws], wk + ((ws * 9 + bs) * 2 + 1) * WPL);
                }
                #pragma unroll
                for (int ws = 0; ws < 2; ws++) MMA(D[ws][ye], Ax[0][0], Bh[ws][pe]);
                #pragma unroll
                for (int ws = 0; ws < 2; ws++) MMA(D[ws][yo], Ax[1][0], Bh[ws][po]);
                #pragma unroll
                for (int ws = 0; ws < 2; ws++) MMA(D[ws][ye], Ax[0][1], Bh[ws][pe]);
                #pragma unroll
                for (int ws = 0; ws < 2; ws++) MMA(D[ws][yo], Ax[1][1], Bh[ws][po]);
                #pragma unroll
                for (int ws = 0; ws < 2; ws++) MMA(D[ws][ye], Ax[0][0], Blp[ws]);
                #pragma unroll
                for (int ws = 0; ws < 2; ws++) MMA(D[ws][yo], Ax[1][0], Blo[ws]);
                #pragma unroll
                for (int ws = 0; ws < 2; ws++) MMA(D[ws][yo], Ax[0][0], Bh[ws][bs]);
                #pragma unroll
                for (int ws = 0; ws < 2; ws++) MMA(D[ws][yo], Ax[0][1], Bh[ws][bs]);
                #pragma unroll
                for (int ws = 0; ws < 2; ws++) MMA(D[ws][yo], Ax[0][0], Blb[ws]);
            }
            __syncthreads();

            // ================= phase B =================
            // MMA t = 4..7 (reads y8-15, staged in phase A)
            #pragma unroll
            for (int t = 4; t < 8; t++) {
                const int ye = 2 * t, yo = 2 * t + 1;
                const int pe = PCY[ye], po = PCY[yo], bs = 4 + po;
                uint32_t Ax[2][2][4];
                #pragma unroll
                for (int yy = 0; yy < 2; yy++)
                    #pragma unroll
                    for (int hl = 0; hl < 2; hl++)
                        ldmx4(Ax[yy][hl], xlm + hl * XHL + (ye + yy) * YPL);
                uint32_t Blp[2][2], Blo[2][2], Blb[2][2];
                #pragma unroll
                for (int ws = 0; ws < 2; ws++) {
                    ldmx2(Blp[ws], wk + ((ws * 9 + pe) * 2 + 1) * WPL);
                    ldmx2(Blo[ws], wk + ((ws * 9 + po) * 2 + 1) * WPL);
                    ldmx2(Blb[ws], wk + ((ws * 9 + bs) * 2 + 1) * WPL);
                }
                #pragma unroll
                for (int ws = 0; ws < 2; ws++) MMA(D[ws][ye], Ax[0][0], Bh[ws][pe]);
                #pragma unroll
                for (int ws = 0; ws < 2; ws++) MMA(D[ws][yo], Ax[1][0], Bh[ws][po]);
                #pragma unroll
                for (int ws = 0; ws < 2; ws++) MMA(D[ws][ye], Ax[0][1], Bh[ws][pe]);
                #pragma unroll
                for (int ws = 0; ws < 2; ws++) MMA(D[ws][yo], Ax[1][1], Bh[ws][po]);
                #pragma unroll
                for (int ws = 0; ws < 2; ws++) MMA(D[ws][ye], Ax[0][0], Blp[ws]);
                #pragma unroll
                for (int ws = 0; ws < 2; ws++) MMA(D[ws][yo], Ax[1][0], Blo[ws]);
                #pragma unroll
                for (int ws = 0; ws < 2; ws++) MMA(D[ws][yo], Ax[0][0], Bh[ws][bs]);
                #pragma unroll
                for (int ws = 0; ws < 2; ws++) MMA(D[ws][yo], Ax[0][1], Bh[ws][bs]);
                #pragma unroll
                for (int ws = 0; ws < 2; ws++) MMA(D[ws][yo], Ax[0][0], Blb[ws]);
            }
            // STS half0 (y0-7) of NEXT ib from freshly prefetched pf
            if (vnext) {
                #pragma unroll
                for (int k = 0; k < 4; k++) {
                    if (half == 0) {
                        float e0[4] = {pf[2*k].x, pf[2*k].y, pf[2*k].z, pf[2*k].w};
                        float e1[4] = {pf[2*k+1].x, pf[2*k+1].y, pf[2*k+1].z, pf[2*k+1].w};
                        #pragma unroll
                        for (int c = 0; c < 4; c++) {
                            int y = sq4 * 4 + c;
                            __nv_bfloat16 h0 = __float2bfloat16(e0[c]);
                            __nv_bfloat16 h1 = __float2bfloat16(e1[c]);
                            __nv_bfloat16 l0 = __float2bfloat16(e0[c] - __bfloat162float(h0));
                            __nv_bfloat16 l1 = __float2bfloat16(e1[c] - __bfloat162float(h1));
                            uint32_t hw = (uint32_t)__bfloat16_as_ushort(h0) | ((uint32_t)__bfloat16_as_ushort(h1) << 16);
                            uint32_t lw = (uint32_t)__bfloat16_as_ushort(l0) | ((uint32_t)__bfloat16_as_ushort(l1) << 16);
                            char* d0 = xsm + y * YPL + spp[k] * PSTR + sip * 4;
                            *(uint32_t*)d0 = hw;
                            *(uint32_t*)(d0 + XHL) = lw;
                        }
                    }
                }
            }
            __syncthreads();
        }

        // ---- bilinear epilogue + store (exact fp32) ----
        #pragma unroll
        for (int e = 0; e < 4; e++) {
            const int p = p0 + pt * 16 + r + ((e >> 1) * 8);
            const int co = cout + (e & 1);
            float o[16];
            #pragma unroll
            for (int y = 0; y < 16; y++) o[y] = 0.0f;

            if (branch == 0) {
                #pragma unroll
                for (int n = 0; n < 192; n++)
                    o[GPT.k[n]] += GPT.s[n] * D[0][GPT.a[n]][e] * D[1][GPT.b[n]][e];
                #pragma unroll
                for (int y = 0; y < 16; y++) o[y] *= 1e-5f;
            } else {
                #pragma unroll
                for (int n = 0; n < 81; n++)
                    o[JT.k[n]] += JT.s[n] * D[0][JT.a[n]][e] * D[1][JT.b[n]][e];
                const float rr = __ldg(ref + (size_t)p * 16 + 15);
                #pragma unroll
                for (int y = 0; y < 16; y++) o[y] *= rr;
            }

            float4* op = (float4*)(out + ((size_t)p * 128 + co) * 16);
            op[0] = make_float4(o[0],  o[1],  o[2],  o[3]);
            op[1] = make_float4(o[4],  o[5],  o[6],  o[7]);
            op[2] = make_float4(o[8],  o[9],  o[10], o[11]);
            op[3] = make_float4(o[12], o[13], o[14], o[15]);
        }
    }
}

extern "C" void kernel_launch(void* const* d_in, const int* in_sizes, int n_in,
                              void* d_out, int out_size) {
    const float* x   = (const float*)d_in[0];
    const float* ref = (const float*)d_in[1];
    const float* wg1 = (const float*)d_in[2];
    const float* wg2 = (const float*)d_in[3];
    const float* wj1 = (const float*)d_in[4];
    const float* wj2 = (const float*)d_in[5];
    float* out = (float*)d_out;

    const int nPos = in_sizes[0] / (64 * 16);   // 16384

    cudaFuncSetAttribute(gbl_kernel, cudaFuncAttributeMaxDynamicSharedMemorySize, SMEM_BYTES);
    dim3 grid(37, 4);
    gbl_kernel<<<grid, THREADS, SMEM_BYTES>>>(x, ref, wg1, wg2, wj1, wj2, out, nPos);
}

// round 15
// speedup vs baseline: 1.4926x; 1.4926x over previous
#include <cuda_runtime.h>
#include <cuda_fp16.h>
#include <cstdint>

__host__ __device__ constexpr int PC4(int x) {
    return ((x >> 0) & 1) + ((x >> 1) & 1) + ((x >> 2) & 1) + ((x >> 3) & 1);
}
__host__ __device__ constexpr float SGN(int a, int b) {
    int s = 0; int aa = a >> 1;
    while (aa) { s += PC4(aa & b); aa >>= 1; }
    return (s & 1) ? -1.0f : 1.0f;
}
struct GPTab { int a[192]; int b[192]; int k[192]; float s[192]; };
__host__ __device__ constexpr GPTab make_gp() {
    GPTab t{}; int n = 0;
    for (int a = 0; a < 16; a++)
        for (int b = 0; b < 16; b++)
            if (!(a & b & 1)) { t.a[n]=a; t.b[n]=b; t.k[n]=a^b; t.s[n]=SGN(a,b); n++; }
    return t;
}
struct JTab { int a[81]; int b[81]; int k[81]; float s[81]; };
__host__ __device__ constexpr JTab make_j() {
    JTab t{}; int n = 0;
    for (int i = 0; i < 16; i++)
        for (int j = 0; j < 16; j++)
            if ((i | j) == 15) {
                int p = i^15, q = j^15, k = i&j, r = k^15;
                t.a[n]=i; t.b[n]=j; t.k[n]=k;
                t.s[n]=SGN(i,p)*SGN(j,q)*SGN(p,q)*SGN(k,r); n++;
            }
    return t;
}
__device__ constexpr GPTab GPT = make_gp();
__device__ constexpr JTab  JT  = make_j();

#define MMA(d, a, b) \
    asm("mma.sync.aligned.m16n8k16.row.col.f32.f16.f16.f32 " \
        "{%0,%1,%2,%3}, {%4,%5,%6,%7}, {%8,%9}, {%0,%1,%2,%3};" \
        : "+f"(d[0]), "+f"(d[1]), "+f"(d[2]), "+f"(d[3]) \
        : "r"(a[0]), "r"(a[1]), "r"(a[2]), "r"(a[3]), "r"(b[0]), "r"(b[1]))

__device__ __forceinline__ void ldmx4(uint32_t* r, uint32_t a) {
    asm volatile("ldmatrix.sync.aligned.m8n8.x4.shared.b16 {%0,%1,%2,%3}, [%4];"
        : "=r"(r[0]), "=r"(r[1]), "=r"(r[2]), "=r"(r[3]) : "r"(a));
}
__device__ __forceinline__ void ldmx2(uint32_t* r, uint32_t a) {
    asm volatile("ldmatrix.sync.aligned.m8n8.x2.shared.b16 {%0,%1}, [%2];"
        : "=r"(r[0]), "=r"(r[1]) : "r"(a));
}
__device__ __forceinline__ uint32_t smem_u32(const void* p) {
    uint32_t a;
    asm("{ .reg .u64 t; cvta.to.shared.u64 t, %1; cvt.u32.u64 %0, t; }" : "=r"(a) : "l"(p));
    return a;
}

#define THREADS 256
#define JSTR 144
#define WPL  (32 * JSTR)
#define WSM_BYTES (36 * WPL)        // 165888
#define PSTR 48
#define YPL  (32 * PSTR + 16)       // 1552
#define XSM_BYTES (16 * YPL)        // 24832 (single fp16 plane per y)
#define SMEM_BYTES (WSM_BYTES + XSM_BYTES)

__global__ __launch_bounds__(THREADS, 1)
void gbl_kernel(const float* __restrict__ x, const float* __restrict__ ref,
                const float* __restrict__ wg1, const float* __restrict__ wg2,
                const float* __restrict__ wj1, const float* __restrict__ wj2,
                float* __restrict__ out, int nPos)
{
    extern __shared__ char sm[];
    char* wsm = sm;
    char* xsm = sm + WSM_BYTES;

    const int tid  = threadIdx.x;
    const int wid  = tid >> 5;
    const int lane = tid & 31;
    const int pt = wid >> 2;
    const int jt = wid & 3;
    const int r  = lane >> 2;
    const int q  = lane & 3;

    const int group  = blockIdx.y;
    const int branch = group >> 1;
    const int chalf  = group & 1;
    const float* wA = branch ? wj1 : wg1;
    const float* wB = branch ? wj2 : wg2;

    // ---- stage weights (fp32 -> fp16 hi/lo) ----
    for (int e = tid; e < 36864; e += THREADS) {
        int ws = e / 18432;
        int rem = e - ws * 18432;
        int j = rem / 576;
        int rem2 = rem - j * 576;
        int i = rem2 / 9;
        int b = rem2 - i * 9;
        const float* src = ws ? wB : wA;
        float v = src[(chalf * 32 + j) * 576 + i * 9 + b];
        __half h = __float2half(v);
        __half l = __float2half(v - __half2float(h));
        char* rp = wsm + ((ws * 9 + b) * 2) * WPL + j * JSTR + i * 2;
        *(__half*)rp = h;
        *(__half*)(rp + WPL) = l;
    }
    __syncthreads();

    const int cout = branch * 64 + chalf * 32 + jt * 8 + 2 * q;
    const int nChunk = nPos >> 5;
    const float4* xg4 = (const float4*)x;

    const uint32_t wlm = smem_u32(wsm) + (jt * 8 + (lane & 7)) * JSTR
                         + ((lane >> 3) & 1) * 16;
    const uint32_t xlm = smem_u32(xsm)
                         + (pt * 16 + ((lane >> 3) & 1) * 8 + (lane & 7)) * PSTR
                         + (lane >> 4) * 16;

    const int sq4 = tid & 3, sip = (tid >> 2) & 7;
    const int spp[4] = {tid >> 5, (tid + THREADS) >> 5,
                        (tid + 2 * THREADS) >> 5, (tid + 3 * THREADS) >> 5};

    float4 pf[8];
    #pragma unroll
    for (int k = 0; k < 4; k++) {
        const float4* g = xg4 + ((size_t)((blockIdx.x << 5) + spp[k]) * 64 + 2 * sip) * 4 + sq4;
        pf[2 * k]     = g[0];
        pf[2 * k + 1] = g[4];
    }

    for (int chunk = blockIdx.x; chunk < nChunk; chunk += gridDim.x) {
        const int p0 = chunk << 5;

        float D[2][16][4];
        #pragma unroll
        for (int ws = 0; ws < 2; ws++)
            #pragma unroll
            for (int y = 0; y < 16; y++)
                #pragma unroll
                for (int k = 0; k < 4; k++) D[ws][y][k] = 0.0f;

        for (int ib = 0; ib < 4; ib++) {
            __syncthreads();
            // ---- convert + store prefetched k-block (fp16, hi only) ----
            #pragma unroll
            for (int k = 0; k < 4; k++) {
                float e0[4] = {pf[2*k].x, pf[2*k].y, pf[2*k].z, pf[2*k].w};
                float e1[4] = {pf[2*k+1].x, pf[2*k+1].y, pf[2*k+1].z, pf[2*k+1].w};
                #pragma unroll
                for (int c = 0; c < 4; c++) {
                    int y = sq4 * 4 + c;
                    __half h0 = __float2half(e0[c]);
                    __half h1 = __float2half(e1[c]);
                    uint32_t hw = (uint32_t)__half_as_ushort(h0) |
                                  ((uint32_t)__half_as_ushort(h1) << 16);
                    *(uint32_t*)(xsm + y * YPL + spp[k] * PSTR + sip * 4) = hw;
                }
            }
            __syncthreads();

            {   // prefetch next k-block / next chunk's first
                int nib = ib + 1;
                int nch = chunk;
                if (nib == 4) { nib = 0; nch = chunk + gridDim.x; }
                if (nch < nChunk) {
                    const int np0 = nch << 5;
                    #pragma unroll
                    for (int k = 0; k < 4; k++) {
                        const float4* g = xg4 + ((size_t)(np0 + spp[k]) * 64 + nib * 16 + 2 * sip) * 4 + sq4;
                        pf[2 * k]     = g[0];
                        pf[2 * k + 1] = g[4];
                    }
                }
            }

            // ---- hi w fragments cached (both wsets) ----
            uint32_t Bh[2][9][2];
            const uint32_t wk = wlm + ib * 32;
            #pragma unroll
            for (int ws = 0; ws < 2; ws++)
                #pragma unroll
                for (int b = 0; b < 9; b++)
                    ldmx2(Bh[ws][b], wk + ((ws * 9 + b) * 2) * WPL);

            // lo fragments grouped by shared (pe,po,bs) triple
            uint32_t Bla[2][2], Blb[2][2], Blc[2][2];
#define LOAD_BL(PE, PO, BS) \
            { \
                _Pragma("unroll") \
                for (int ws = 0; ws < 2; ws++) { \
                    ldmx2(Bla[ws], wk + ((ws * 9 + (PE)) * 2 + 1) * WPL); \
                    ldmx2(Blb[ws], wk + ((ws * 9 + (PO)) * 2 + 1) * WPL); \
                    ldmx2(Blc[ws], wk + ((ws * 9 + (BS)) * 2 + 1) * WPL); \
                } \
            }
#define DO_T(T, PE, PO, BS) \
            { \
                const int ye = 2 * (T), yo = ye + 1; \
                uint32_t Ax[2][4]; \
                ldmx4(Ax[0], xlm + ye * YPL); \
                ldmx4(Ax[1], xlm + yo * YPL); \
                _Pragma("unroll") \
                for (int ws = 0; ws < 2; ws++) MMA(D[ws][ye], Ax[0], Bh[ws][PE]); \
                _Pragma("unroll") \
                for (int ws = 0; ws < 2; ws++) MMA(D[ws][yo], Ax[1], Bh[ws][PO]); \
                _Pragma("unroll") \
                for (int ws = 0; ws < 2; ws++) MMA(D[ws][ye], Ax[0], Bla[ws]); \
                _Pragma("unroll") \
                for (int ws = 0; ws < 2; ws++) MMA(D[ws][yo], Ax[1], Blb[ws]); \
                _Pragma("unroll") \
                for (int ws = 0; ws < 2; ws++) MMA(D[ws][yo], Ax[0], Bh[ws][BS]); \
                _Pragma("unroll") \
                for (int ws = 0; ws < 2; ws++) MMA(D[ws][yo], Ax[0], Blc[ws]); \
            }
            // PCY-derived triples: t:(pe,po,bs) = 0:(0,1,5) {1,2,4}:(1,2,6) {3,5,6}:(2,3,7) 7:(3,4,8)
            LOAD_BL(0, 1, 5); DO_T(0, 0, 1, 5);
            LOAD_BL(1, 2, 6); DO_T(1, 1, 2, 6); DO_T(2, 1, 2, 6); DO_T(4, 1, 2, 6);
            LOAD_BL(2, 3, 7); DO_T(3, 2, 3, 7); DO_T(5, 2, 3, 7); DO_T(6, 2, 3, 7);
            LOAD_BL(3, 4, 8); DO_T(7, 3, 4, 8);
#undef LOAD_BL
#undef DO_T
        }

        // ---- bilinear epilogue + store (exact fp32) ----
        #pragma unroll
        for (int e = 0; e < 4; e++) {
            const int p = p0 + pt * 16 + r + ((e >> 1) * 8);
            const int co = cout + (e & 1);
            float o[16];
            #pragma unroll
            for (int y = 0; y < 16; y++) o[y] = 0.0f;

            if (branch == 0) {
                #pragma unroll
                for (int n = 0; n < 192; n++)
                    o[GPT.k[n]] += GPT.s[n] * D[0][GPT.a[n]][e] * D[1][GPT.b[n]][e];
                #pragma unroll
                for (int y = 0; y < 16; y++) o[y] *= 1e-5f;
            } else {
                #pragma unroll
                for (int n = 0; n < 81; n++)
                    o[JT.k[n]] += JT.s[n] * D[0][JT.a[n]][e] * D[1][JT.b[n]][e];
                const float rr = __ldg(ref + (size_t)p * 16 + 15);
                #pragma unroll
                for (int y = 0; y < 16; y++) o[y] *= rr;
            }

            float4* op = (float4*)(out + ((size_t)p * 128 + co) * 16);
            op[0] = make_float4(o[0],  o[1],  o[2],  o[3]);
            op[1] = make_float4(o[4],  o[5],  o[6],  o[7]);
            op[2] = make_float4(o[8],  o[9],  o[10], o[11]);
            op[3] = make_float4(o[12], o[13], o[14], o[15]);
        }
    }
}

extern "C" void kernel_launch(void* const* d_in, const int* in_sizes, int n_in,
                              void* d_out, int out_size) {
    const float* x   = (const float*)d_in[0];
    const float* ref = (const float*)d_in[1];
    const float* wg1 = (const float*)d_in[2];
    const float* wg2 = (const float*)d_in[3];
    const float* wj1 = (const float*)d_in[4];
    const float* wj2 = (const float*)d_in[5];
    float* out = (float*)d_out;

    const int nPos = in_sizes[0] / (64 * 16);   // 16384

    cudaFuncSetAttribute(gbl_kernel, cudaFuncAttributeMaxDynamicSharedMemorySize, SMEM_BYTES);
    dim3 grid(37, 4);
    gbl_kernel<<<grid, THREADS, SMEM_BYTES>>>(x, ref, wg1, wg2, wj1, wj2, out, nPos);
}

// round 16
// speedup vs baseline: 1.6667x; 1.1166x over previous
#include <cuda_runtime.h>
#include <cuda_fp16.h>
#include <cstdint>

__host__ __device__ constexpr int PC4(int x) {
    return ((x >> 0) & 1) + ((x >> 1) & 1) + ((x >> 2) & 1) + ((x >> 3) & 1);
}
__host__ __device__ constexpr float SGN(int a, int b) {
    int s = 0; int aa = a >> 1;
    while (aa) { s += PC4(aa & b); aa >>= 1; }
    return (s & 1) ? -1.0f : 1.0f;
}
struct GPTab { int a[192]; int b[192]; int k[192]; float s[192]; };
__host__ __device__ constexpr GPTab make_gp() {
    GPTab t{}; int n = 0;
    for (int a = 0; a < 16; a++)
        for (int b = 0; b < 16; b++)
            if (!(a & b & 1)) { t.a[n]=a; t.b[n]=b; t.k[n]=a^b; t.s[n]=SGN(a,b); n++; }
    return t;
}
struct JTab { int a[81]; int b[81]; int k[81]; float s[81]; };
__host__ __device__ constexpr JTab make_j() {
    JTab t{}; int n = 0;
    for (int i = 0; i < 16; i++)
        for (int j = 0; j < 16; j++)
            if ((i | j) == 15) {
                int p = i^15, q = j^15, k = i&j, r = k^15;
                t.a[n]=i; t.b[n]=j; t.k[n]=k;
                t.s[n]=SGN(i,p)*SGN(j,q)*SGN(p,q)*SGN(k,r); n++;
            }
    return t;
}
__device__ constexpr GPTab GPT = make_gp();
__device__ constexpr JTab  JT  = make_j();

#define MMA(d, a, b) \
    asm("mma.sync.aligned.m16n8k16.row.col.f32.f16.f16.f32 " \
        "{%0,%1,%2,%3}, {%4,%5,%6,%7}, {%8,%9}, {%0,%1,%2,%3};" \
        : "+f"(d[0]), "+f"(d[1]), "+f"(d[2]), "+f"(d[3]) \
        : "r"(a[0]), "r"(a[1]), "r"(a[2]), "r"(a[3]), "r"(b[0]), "r"(b[1]))

__device__ __forceinline__ void ldmx4(uint32_t* r, uint32_t a) {
    asm volatile("ldmatrix.sync.aligned.m8n8.x4.shared.b16 {%0,%1,%2,%3}, [%4];"
        : "=r"(r[0]), "=r"(r[1]), "=r"(r[2]), "=r"(r[3]) : "r"(a));
}
__device__ __forceinline__ void ldmx2(uint32_t* r, uint32_t a) {
    asm volatile("ldmatrix.sync.aligned.m8n8.x2.shared.b16 {%0,%1}, [%2];"
        : "=r"(r[0]), "=r"(r[1]) : "r"(a));
}
__device__ __forceinline__ uint32_t smem_u32(const void* p) {
    uint32_t a;
    asm("{ .reg .u64 t; cvta.to.shared.u64 t, %1; cvt.u32.u64 %0, t; }" : "=r"(a) : "l"(p));
    return a;
}

#define THREADS 256
#define JSTR 144
#define WPL  (32 * JSTR)
#define WSM_BYTES (18 * WPL)        // 82944 (single fp16 plane per (ws,b))
#define PSTR 48
#define YPL  (32 * PSTR + 16)       // 1552
#define XSM_BYTES (16 * YPL)        // 24832
#define SMEM_BYTES (WSM_BYTES + XSM_BYTES)   // 107776

__global__ __launch_bounds__(THREADS, 1)
void gbl_kernel(const float* __restrict__ x, const float* __restrict__ ref,
                const float* __restrict__ wg1, const float* __restrict__ wg2,
                const float* __restrict__ wj1, const float* __restrict__ wj2,
                float* __restrict__ out, int nPos)
{
    extern __shared__ char sm[];
    char* wsm = sm;
    char* xsm = sm + WSM_BYTES;

    const int tid  = threadIdx.x;
    const int wid  = tid >> 5;
    const int lane = tid & 31;
    const int pt = wid >> 2;
    const int jt = wid & 3;
    const int r  = lane >> 2;
    const int q  = lane & 3;

    const int group  = blockIdx.y;
    const int branch = group >> 1;
    const int chalf  = group & 1;
    const float* wA = branch ? wj1 : wg1;
    const float* wB = branch ? wj2 : wg2;

    // ---- stage weights (fp32 -> fp16 single) ----
    for (int e = tid; e < 36864; e += THREADS) {
        int ws = e / 18432;
        int rem = e - ws * 18432;
        int j = rem / 576;
        int rem2 = rem - j * 576;
        int i = rem2 / 9;
        int b = rem2 - i * 9;
        const float* src = ws ? wB : wA;
        float v = src[(chalf * 32 + j) * 576 + i * 9 + b];
        *(__half*)(wsm + (ws * 9 + b) * WPL + j * JSTR + i * 2) = __float2half(v);
    }
    __syncthreads();

    const int cout = branch * 64 + chalf * 32 + jt * 8 + 2 * q;
    const int nChunk = nPos >> 5;
    const float4* xg4 = (const float4*)x;

    const uint32_t wlm = smem_u32(wsm) + (jt * 8 + (lane & 7)) * JSTR
                         + ((lane >> 3) & 1) * 16;
    const uint32_t xlm = smem_u32(xsm)
                         + (pt * 16 + ((lane >> 3) & 1) * 8 + (lane & 7)) * PSTR
                         + (lane >> 4) * 16;

    const int sq4 = tid & 3, sip = (tid >> 2) & 7;
    const int spp[4] = {tid >> 5, (tid + THREADS) >> 5,
                        (tid + 2 * THREADS) >> 5, (tid + 3 * THREADS) >> 5};

    float4 pf[8];
    #pragma unroll
    for (int k = 0; k < 4; k++) {
        const float4* g = xg4 + ((size_t)((blockIdx.x << 5) + spp[k]) * 64 + 2 * sip) * 4 + sq4;
        pf[2 * k]     = g[0];
        pf[2 * k + 1] = g[4];
    }

    for (int chunk = blockIdx.x; chunk < nChunk; chunk += gridDim.x) {
        const int p0 = chunk << 5;

        float D[2][16][4];
        #pragma unroll
        for (int ws = 0; ws < 2; ws++)
            #pragma unroll
            for (int y = 0; y < 16; y++)
                #pragma unroll
                for (int k = 0; k < 4; k++) D[ws][y][k] = 0.0f;

        for (int ib = 0; ib < 4; ib++) {
            __syncthreads();
            // ---- convert + store prefetched k-block (fp16) ----
            #pragma unroll
            for (int k = 0; k < 4; k++) {
                float e0[4] = {pf[2*k].x, pf[2*k].y, pf[2*k].z, pf[2*k].w};
                float e1[4] = {pf[2*k+1].x, pf[2*k+1].y, pf[2*k+1].z, pf[2*k+1].w};
                #pragma unroll
                for (int c = 0; c < 4; c++) {
                    int y = sq4 * 4 + c;
                    __half h0 = __float2half(e0[c]);
                    __half h1 = __float2half(e1[c]);
                    uint32_t hw = (uint32_t)__half_as_ushort(h0) |
                                  ((uint32_t)__half_as_ushort(h1) << 16);
                    *(uint32_t*)(xsm + y * YPL + spp[k] * PSTR + sip * 4) = hw;
                }
            }
            __syncthreads();

            {   // prefetch next k-block / next chunk's first
                int nib = ib + 1;
                int nch = chunk;
                if (nib == 4) { nib = 0; nch = chunk + gridDim.x; }
                if (nch < nChunk) {
                    const int np0 = nch << 5;
                    #pragma unroll
                    for (int k = 0; k < 4; k++) {
                        const float4* g = xg4 + ((size_t)(np0 + spp[k]) * 64 + nib * 16 + 2 * sip) * 4 + sq4;
                        pf[2 * k]     = g[0];
                        pf[2 * k + 1] = g[4];
                    }
                }
            }

            // ---- w fragments cached (both wsets, 9 maps) ----
            uint32_t Bh[2][9][2];
            const uint32_t wk = wlm + ib * 32;
            #pragma unroll
            for (int ws = 0; ws < 2; ws++)
                #pragma unroll
                for (int b = 0; b < 9; b++)
                    ldmx2(Bh[ws][b], wk + (ws * 9 + b) * WPL);

#define DO_T(T, PE, PO, BS) \
            { \
                const int ye = 2 * (T), yo = ye + 1; \
                uint32_t Ax[2][4]; \
                ldmx4(Ax[0], xlm + ye * YPL); \
                ldmx4(Ax[1], xlm + yo * YPL); \
                _Pragma("unroll") \
                for (int ws = 0; ws < 2; ws++) MMA(D[ws][ye], Ax[0], Bh[ws][PE]); \
                _Pragma("unroll") \
                for (int ws = 0; ws < 2; ws++) MMA(D[ws][yo], Ax[1], Bh[ws][PO]); \
                _Pragma("unroll") \
                for (int ws = 0; ws < 2; ws++) MMA(D[ws][yo], Ax[0], Bh[ws][BS]); \
            }
            // t:(pe,po,bs) = 0:(0,1,5) {1,2,4}:(1,2,6) {3,5,6}:(2,3,7) 7:(3,4,8)
            DO_T(0, 0, 1, 5);
            DO_T(1, 1, 2, 6); DO_T(2, 1, 2, 6); DO_T(4, 1, 2, 6);
            DO_T(3, 2, 3, 7); DO_T(5, 2, 3, 7); DO_T(6, 2, 3, 7);
            DO_T(7, 3, 4, 8);
#undef DO_T
        }

        // ---- bilinear epilogue + store (exact fp32) ----
        #pragma unroll
        for (int e = 0; e < 4; e++) {
            const int p = p0 + pt * 16 + r + ((e >> 1) * 8);
            const int co = cout + (e & 1);
            float o[16];
            #pragma unroll
            for (int y = 0; y < 16; y++) o[y] = 0.0f;

            if (branch == 0) {
                #pragma unroll
                for (int n = 0; n < 192; n++)
                    o[GPT.k[n]] += GPT.s[n] * D[0][GPT.a[n]][e] * D[1][GPT.b[n]][e];
                #pragma unroll
                for (int y = 0; y < 16; y++) o[y] *= 1e-5f;
            } else {
                #pragma unroll
                for (int n = 0; n < 81; n++)
                    o[JT.k[n]] += JT.s[n] * D[0][JT.a[n]][e] * D[1][JT.b[n]][e];
                const float rr = __ldg(ref + (size_t)p * 16 + 15);
                #pragma unroll
                for (int y = 0; y < 16; y++) o[y] *= rr;
            }

            float4* op = (float4*)(out + ((size_t)p * 128 + co) * 16);
            op[0] = make_float4(o[0],  o[1],  o[2],  o[3]);
            op[1] = make_float4(o[4],  o[5],  o[6],  o[7]);
            op[2] = make_float4(o[8],  o[9],  o[10], o[11]);
            op[3] = make_float4(o[12], o[13], o[14], o[15]);
        }
    }
}

extern "C" void kernel_launch(void* const* d_in, const int* in_sizes, int n_in,
                              void* d_out, int out_size) {
    const float* x   = (const float*)d_in[0];
    const float* ref = (const float*)d_in[1];
    const float* wg1 = (const float*)d_in[2];
    const float* wg2 = (const float*)d_in[3];
    const float* wj1 = (const float*)d_in[4];
    const float* wj2 = (const float*)d_in[5];
    float* out = (float*)d_out;

    const int nPos = in_sizes[0] / (64 * 16);   // 16384

    cudaFuncSetAttribute(gbl_kernel, cudaFuncAttributeMaxDynamicSharedMemorySize, SMEM_BYTES);
    dim3 grid(37, 4);
    gbl_kernel<<<grid, THREADS, SMEM_BYTES>>>(x, ref, wg1, wg2, wj1, wj2, out, nPos);
}

// round 17
// speedup vs baseline: 1.7751x; 1.0651x over previous
#include <cuda_runtime.h>
#include <cuda_fp16.h>
#include <cstdint>

__host__ __device__ constexpr int PC4(int x) {
    return ((x >> 0) & 1) + ((x >> 1) & 1) + ((x >> 2) & 1) + ((x >> 3) & 1);
}
__host__ __device__ constexpr float SGN(int a, int b) {
    int s = 0; int aa = a >> 1;
    while (aa) { s += PC4(aa & b); aa >>= 1; }
    return (s & 1) ? -1.0f : 1.0f;
}
struct GPTab { int a[192]; int b[192]; int k[192]; float s[192]; };
__host__ __device__ constexpr GPTab make_gp() {
    GPTab t{}; int n = 0;
    for (int a = 0; a < 16; a++)
        for (int b = 0; b < 16; b++)
            if (!(a & b & 1)) { t.a[n]=a; t.b[n]=b; t.k[n]=a^b; t.s[n]=SGN(a,b); n++; }
    return t;
}
struct JTab { int a[81]; int b[81]; int k[81]; float s[81]; };
__host__ __device__ constexpr JTab make_j() {
    JTab t{}; int n = 0;
    for (int i = 0; i < 16; i++)
        for (int j = 0; j < 16; j++)
            if ((i | j) == 15) {
                int p = i^15, q = j^15, k = i&j, r = k^15;
                t.a[n]=i; t.b[n]=j; t.k[n]=k;
                t.s[n]=SGN(i,p)*SGN(j,q)*SGN(p,q)*SGN(k,r); n++;
            }
    return t;
}
__device__ constexpr GPTab GPT = make_gp();
__device__ constexpr JTab  JT  = make_j();

#define MMA(d, a, b) \
    asm("mma.sync.aligned.m16n8k16.row.col.f32.f16.f16.f32 " \
        "{%0,%1,%2,%3}, {%4,%5,%6,%7}, {%8,%9}, {%0,%1,%2,%3};" \
        : "+f"(d[0]), "+f"(d[1]), "+f"(d[2]), "+f"(d[3]) \
        : "r"(a[0]), "r"(a[1]), "r"(a[2]), "r"(a[3]), "r"(b[0]), "r"(b[1]))

__device__ __forceinline__ void ldmx4(uint32_t* r, uint32_t a) {
    asm volatile("ldmatrix.sync.aligned.m8n8.x4.shared.b16 {%0,%1,%2,%3}, [%4];"
        : "=r"(r[0]), "=r"(r[1]), "=r"(r[2]), "=r"(r[3]) : "r"(a));
}
__device__ __forceinline__ void ldmx2(uint32_t* r, uint32_t a) {
    asm volatile("ldmatrix.sync.aligned.m8n8.x2.shared.b16 {%0,%1}, [%2];"
        : "=r"(r[0]), "=r"(r[1]) : "r"(a));
}
__device__ __forceinline__ uint32_t smem_u32(const void* p) {
    uint32_t a;
    asm("{ .reg .u64 t; cvta.to.shared.u64 t, %1; cvt.u32.u64 %0, t; }" : "=r"(a) : "l"(p));
    return a;
}

#define THREADS 256
#define JSTR 144
#define WPL  (32 * JSTR)
#define WSM_BYTES (18 * WPL)        // 82944
#define PSTR 48
#define YPL  (32 * PSTR + 16)       // 1552
#define XBUF (16 * YPL)             // 24832 per buffer
#define SMEM_BYTES (WSM_BYTES + 2 * XBUF)   // 132608

__global__ __launch_bounds__(THREADS, 1)
void gbl_kernel(const float* __restrict__ x, const float* __restrict__ ref,
                const float* __restrict__ wg1, const float* __restrict__ wg2,
                const float* __restrict__ wj1, const float* __restrict__ wj2,
                float* __restrict__ out, int nPos)
{
    extern __shared__ char sm[];
    char* wsm = sm;
    char* xsm = sm + WSM_BYTES;   // 2 buffers of XBUF

    const int tid  = threadIdx.x;
    const int wid  = tid >> 5;
    const int lane = tid & 31;
    const int pt = wid >> 2;
    const int jt = wid & 3;
    const int r  = lane >> 2;
    const int q  = lane & 3;

    const int group  = blockIdx.y;
    const int branch = group >> 1;
    const int chalf  = group & 1;
    const float* wA = branch ? wj1 : wg1;
    const float* wB = branch ? wj2 : wg2;

    // ---- stage weights (fp32 -> fp16) ----
    for (int e = tid; e < 36864; e += THREADS) {
        int ws = e / 18432;
        int rem = e - ws * 18432;
        int j = rem / 576;
        int rem2 = rem - j * 576;
        int i = rem2 / 9;
        int b = rem2 - i * 9;
        const float* src = ws ? wB : wA;
        float v = src[(chalf * 32 + j) * 576 + i * 9 + b];
        *(__half*)(wsm + (ws * 9 + b) * WPL + j * JSTR + i * 2) = __float2half(v);
    }

    const int cout = branch * 64 + chalf * 32 + jt * 8 + 2 * q;
    const int nChunk = nPos >> 5;
    const float4* xg4 = (const float4*)x;

    const uint32_t wlm = smem_u32(wsm) + (jt * 8 + (lane & 7)) * JSTR
                         + ((lane >> 3) & 1) * 16;
    const uint32_t xlm = smem_u32(xsm)
                         + (pt * 16 + ((lane >> 3) & 1) * 8 + (lane & 7)) * PSTR
                         + (lane >> 4) * 16;

    const int sq4 = tid & 3, sip = (tid >> 2) & 7;
    const int spp[4] = {tid >> 5, (tid + THREADS) >> 5,
                        (tid + 2 * THREADS) >> 5, (tid + 3 * THREADS) >> 5};

    int nMine = 0;
    for (int c = blockIdx.x; c < nChunk; c += gridDim.x) nMine++;
    const int total = nMine * 4;   // linear k-block count for this block

    float4 pf[8];

#define PF_LOAD(KB) \
    { \
        const int _kb = (KB); \
        const int _ch = blockIdx.x + (_kb >> 2) * (int)gridDim.x; \
        const int _ib = _kb & 3; \
        const size_t _p0 = (size_t)_ch << 5; \
        _Pragma("unroll") \
        for (int k = 0; k < 4; k++) { \
            const float4* g = xg4 + ((_p0 + spp[k]) * 64 + _ib * 16 + 2 * sip) * 4 + sq4; \
            pf[2 * k]     = g[0]; \
            pf[2 * k + 1] = g[4]; \
        } \
    }

#define X_STS(KB) \
    { \
        char* xb = xsm + ((KB) & 1) * XBUF; \
        _Pragma("unroll") \
        for (int k = 0; k < 4; k++) { \
            float e0[4] = {pf[2*k].x, pf[2*k].y, pf[2*k].z, pf[2*k].w}; \
            float e1[4] = {pf[2*k+1].x, pf[2*k+1].y, pf[2*k+1].z, pf[2*k+1].w}; \
            _Pragma("unroll") \
            for (int c = 0; c < 4; c++) { \
                int y = sq4 * 4 + c; \
                __half h0 = __float2half(e0[c]); \
                __half h1 = __float2half(e1[c]); \
                uint32_t hw = (uint32_t)__half_as_ushort(h0) | \
                              ((uint32_t)__half_as_ushort(h1) << 16); \
                *(uint32_t*)(xb + y * YPL + spp[k] * PSTR + sip * 4) = hw; \
            } \
        } \
    }

    // ---- pipeline prologue ----
    PF_LOAD(0);
    __syncthreads();     // weights staged (also orders nothing else yet)
    X_STS(0);
    if (total > 1) PF_LOAD(1);

    for (int cl = 0; cl < nMine; cl++) {
        const int chunk = blockIdx.x + cl * gridDim.x;
        const int p0 = chunk << 5;

        float D[2][16][4];
        #pragma unroll
        for (int ws = 0; ws < 2; ws++)
            #pragma unroll
            for (int y = 0; y < 16; y++)
                #pragma unroll
                for (int k = 0; k < 4; k++) D[ws][y][k] = 0.0f;

        #pragma unroll
        for (int ib = 0; ib < 4; ib++) {
            const int kb = cl * 4 + ib;
            __syncthreads();   // publishes STS(kb); frees buf[(kb+1)&1]
            if (kb + 1 < total) X_STS(kb + 1);
            if (kb + 2 < total) PF_LOAD(kb + 2);

            const uint32_t xb = xlm + (kb & 1) * XBUF;

            // w fragments for this ib (both wsets)
            uint32_t Bh[2][9][2];
            const uint32_t wk = wlm + ib * 32;
            #pragma unroll
            for (int ws = 0; ws < 2; ws++)
                #pragma unroll
                for (int b = 0; b < 9; b++)
                    ldmx2(Bh[ws][b], wk + (ws * 9 + b) * WPL);

#define DO_T(T, PE, PO, BS) \
            { \
                const int ye = 2 * (T), yo = ye + 1; \
                uint32_t Ax[2][4]; \
                ldmx4(Ax[0], xb + ye * YPL); \
                ldmx4(Ax[1], xb + yo * YPL); \
                _Pragma("unroll") \
                for (int ws = 0; ws < 2; ws++) MMA(D[ws][ye], Ax[0], Bh[ws][PE]); \
                _Pragma("unroll") \
                for (int ws = 0; ws < 2; ws++) MMA(D[ws][yo], Ax[1], Bh[ws][PO]); \
                _Pragma("unroll") \
                for (int ws = 0; ws < 2; ws++) MMA(D[ws][yo], Ax[0], Bh[ws][BS]); \
            }
            DO_T(0, 0, 1, 5);
            DO_T(1, 1, 2, 6); DO_T(2, 1, 2, 6); DO_T(4, 1, 2, 6);
            DO_T(3, 2, 3, 7); DO_T(5, 2, 3, 7); DO_T(6, 2, 3, 7);
            DO_T(7, 3, 4, 8);
#undef DO_T
        }

        // ---- bilinear epilogue + store (exact fp32) ----
        #pragma unroll
        for (int e = 0; e < 4; e++) {
            const int p = p0 + pt * 16 + r + ((e >> 1) * 8);
            const int co = cout + (e & 1);
            float o[16];
            #pragma unroll
            for (int y = 0; y < 16; y++) o[y] = 0.0f;

            if (branch == 0) {
                #pragma unroll
                for (int n = 0; n < 192; n++)
                    o[GPT.k[n]] += GPT.s[n] * D[0][GPT.a[n]][e] * D[1][GPT.b[n]][e];
                #pragma unroll
                for (int y = 0; y < 16; y++) o[y] *= 1e-5f;
            } else {
                #pragma unroll
                for (int n = 0; n < 81; n++)
                    o[JT.k[n]] += JT.s[n] * D[0][JT.a[n]][e] * D[1][JT.b[n]][e];
                const float rr = __ldg(ref + (size_t)p * 16 + 15);
                #pragma unroll
                for (int y = 0; y < 16; y++) o[y] *= rr;
            }

            float4* op = (float4*)(out + ((size_t)p * 128 + co) * 16);
            op[0] = make_float4(o[0],  o[1],  o[2],  o[3]);
            op[1] = make_float4(o[4],  o[5],  o[6],  o[7]);
            op[2] = make_float4(o[8],  o[9],  o[10], o[11]);
            op[3] = make_float4(o[12], o[13], o[14], o[15]);
        }
    }
#undef PF_LOAD
#undef X_STS
}

extern "C" void kernel_launch(void* const* d_in, const int* in_sizes, int n_in,
                              void* d_out, int out_size) {
    const float* x   = (const float*)d_in[0];
    const float* ref = (const float*)d_in[1];
    const float* wg1 = (const float*)d_in[2];
    const float* wg2 = (const float*)d_in[3];
    const float* wj1 = (const float*)d_in[4];
    const float* wj2 = (const float*)d_in[5];
    float* out = (float*)d_out;

    const int nPos = in_sizes[0] / (64 * 16);   // 16384

    cudaFuncSetAttribute(gbl_kernel, cudaFuncAttributeMaxDynamicSharedMemorySize, SMEM_BYTES);
    dim3 grid(37, 4);
    gbl_kernel<<<grid, THREADS, SMEM_BYTES>>>(x, ref, wg1, wg2, wj1, wj2, out, nPos);
}